// round 14
// baseline (speedup 1.0000x reference)
#include <cuda_runtime.h>
#include <cuda.h>
#include <cuda_bf16.h>
#include <cstdint>

// ============================================================
// Problem constants
// ============================================================
#define KDIM 4096
#define NDIM 4096
#define GROUP 16

#define BM 128
#define BN 128
#define BK 128                   // per stage (two 64-col SW128 sub-tiles)
#define DEPTH 3
#define NK (KDIM / BK)           // 32 k-iterations per tile
#define NTHREADS 288             // 8 compute warps + 1 producer warp
#define NTILES 4096              // (16384/128) * (4096/128)

// ============================================================
// Scratch (device globals: allocation-free rule)
// ============================================================
__device__ __align__(256) __nv_bfloat16 g_qx[(size_t)16384 * KDIM]; // 128 MB
__device__ __align__(256) __nv_bfloat16 g_qw[(size_t)NDIM * KDIM];  //  32 MB
__device__ unsigned g_bar;   // ticket grid-barrier (monotonic across replays)

// ============================================================
// PTX helpers (baseline PTX — toolchain targets sm_103, no tcgen05)
// ============================================================
__device__ __forceinline__ uint32_t smem_to_u32(const void* smem_ptr) {
    uint32_t addr;
    asm("{ .reg .u64 tmp; cvta.to.shared.u64 tmp, %1; cvt.u32.u64 %0, tmp; }"
        : "=r"(addr) : "l"(smem_ptr));
    return addr;
}

#define MBARRIER_INIT(mbar, count) \
    asm volatile("mbarrier.init.shared.b64 [%0], %1;" \
        :: "r"((uint32_t)(mbar)), "r"((uint32_t)(count)) : "memory")

#define MBARRIER_EXPECT_TX(mbar, tx_bytes) \
    asm volatile("mbarrier.arrive.expect_tx.shared.b64 _, [%0], %1;" \
        :: "r"((uint32_t)(mbar)), "r"((uint32_t)(tx_bytes)) : "memory")

#define MBARRIER_ARRIVE(mbar) \
    asm volatile("mbarrier.arrive.shared.b64 _, [%0];" \
        :: "r"((uint32_t)(mbar)) : "memory")

#define MBARRIER_WAIT_PARITY(mbar, parity) do { \
    uint32_t _m = (uint32_t)(mbar); \
    uint32_t _p = (uint32_t)(parity); \
    uint32_t _done; \
    asm volatile( \
        "{\n\t.reg .pred p;\n\t" \
        "mbarrier.try_wait.parity.acquire.cta.shared::cta.b64 p, [%1], %2;\n\t" \
        "selp.b32 %0, 1, 0, p;\n\t}" \
        : "=r"(_done) : "r"(_m), "r"(_p) : "memory"); \
    if (!_done) { \
        asm volatile( \
            "{\n\t.reg .pred P1;\n\t" \
            "WAIT_LOOP_%=:\n\t" \
            "mbarrier.try_wait.parity.acquire.cta.shared::cta.b64 P1, [%0], %1, 0x989680;\n\t" \
            "@P1 bra.uni WAIT_DONE_%=;\n\t" \
            "bra.uni WAIT_LOOP_%=;\n\t" \
            "WAIT_DONE_%=:\n\t}" \
            :: "r"(_m), "r"(_p) : "memory"); \
    } \
} while (0)

__device__ __forceinline__ void tma_load_2d(
    uint32_t smem_addr, const void* tensor_map,
    int32_t cx, int32_t cy, uint32_t mbar)
{
    asm volatile(
        "cp.async.bulk.tensor.2d.shared::cta.global.tile.mbarrier::complete_tx::bytes "
        "[%0], [%1, {%2, %3}], [%4];"
        :: "r"(smem_addr), "l"(tensor_map), "r"(cx), "r"(cy), "r"(mbar)
        : "memory");
}

// SW128 swizzle (matches TMA CU_TENSOR_MAP_SWIZZLE_128B)
__device__ __forceinline__ uint32_t sw128(uint32_t o) {
    return o ^ ((o >> 3) & 0x70);
}

__device__ __forceinline__ void ldsm_x4(uint32_t* r, uint32_t addr) {
    asm volatile(
        "ldmatrix.sync.aligned.m8n8.x4.shared.b16 {%0,%1,%2,%3}, [%4];"
        : "=r"(r[0]), "=r"(r[1]), "=r"(r[2]), "=r"(r[3]) : "r"(addr));
}

__device__ __forceinline__ void mma16816(float* c, const uint32_t* a,
                                         uint32_t b0, uint32_t b1) {
    asm volatile(
        "mma.sync.aligned.m16n8k16.row.col.f32.bf16.bf16.f32 "
        "{%0,%1,%2,%3}, {%4,%5,%6,%7}, {%8,%9}, {%0,%1,%2,%3};"
        : "+f"(c[0]), "+f"(c[1]), "+f"(c[2]), "+f"(c[3])
        : "r"(a[0]), "r"(a[1]), "r"(a[2]), "r"(a[3]), "r"(b0), "r"(b1));
}

// ============================================================
// BFP quantize one group of 16 (fp32 -> exact bf16 post-quant values)
// ============================================================
__device__ __forceinline__ void quant_group(const float* __restrict__ src_base,
                                            __nv_bfloat16* __restrict__ dst_base,
                                            int g)
{
    const float4* src = reinterpret_cast<const float4*>(src_base + (size_t)g * GROUP);
    float4 f0 = src[0], f1 = src[1], f2 = src[2], f3 = src[3];
    float v[GROUP] = {f0.x, f0.y, f0.z, f0.w, f1.x, f1.y, f1.z, f1.w,
                      f2.x, f2.y, f2.z, f2.w, f3.x, f3.y, f3.z, f3.w};
    float m = 0.f;
#pragma unroll
    for (int i = 0; i < GROUP; i++) m = fmaxf(m, fabsf(v[i]));

    union { __nv_bfloat16 h[GROUP]; uint4 u[2]; } pk;
    if (m > 0.f) {
        unsigned e = __float_as_uint(m) >> 23;   // biased exp = 127+floor(log2 m)
        if (e < 8u) e = 8u;
        float scale = __uint_as_float((e - 7u) << 23);     // 2^(exp-7)
        float inv   = __uint_as_float((261u - e) << 23);   // 2^(7-exp) exact
#pragma unroll
        for (int i = 0; i < GROUP; i++) {
            float r = rintf(v[i] * inv);                   // round-half-even
            r = fminf(127.f, fmaxf(-127.f, r));
            pk.h[i] = __float2bfloat16(r * scale);         // exact in bf16
        }
    } else {
#pragma unroll
        for (int i = 0; i < GROUP; i++) pk.h[i] = __float2bfloat16(0.f);
    }
    uint4* dst = reinterpret_cast<uint4*>(dst_base + (size_t)g * GROUP);
    dst[0] = pk.u[0];
    dst[1] = pk.u[1];
}

// ============================================================
// Fused persistent kernel:
//   Phase 1: BFP-quantize X and W (grid-stride, 2 groups/thread/iter)
//   Ticket grid-barrier (all CTAs co-resident: grid = #SMs, 1 CTA/SM)
//   Phase 2: GEMM out = qx @ qw^T + bias (round-11 proven body)
// ============================================================
static constexpr int SMEM_FULL  = 0;
static constexpr int SMEM_EMPTY = SMEM_FULL + 8 * DEPTH;
static constexpr int SUB      = 16384;                      // 128x64 bf16 sub-tile
static constexpr int STAGE_A  = 2 * SUB;                    // 32768 B
static constexpr int STAGE_B  = 2 * SUB;                    // 32768 B
static constexpr int SMEM_A0  = 1024;
static constexpr int SMEM_B0  = SMEM_A0 + DEPTH * STAGE_A;  // 99328
static constexpr int SMEM_TOTAL = SMEM_B0 + DEPTH * STAGE_B; // 197632
static constexpr unsigned STAGE_BYTES = (unsigned)(STAGE_A + STAGE_B); // 65536

__global__ void __launch_bounds__(NTHREADS, 1) bfp_fused_kernel(
    const __grid_constant__ CUtensorMap tma_a,
    const __grid_constant__ CUtensorMap tma_b,
    const float* __restrict__ inp,
    const float* __restrict__ wgt,
    const float* __restrict__ bias,
    float* __restrict__ out,
    int ngx, int ngw)
{
    extern __shared__ char smem[];
    uint32_t sb = smem_to_u32(smem);
    const int tid  = threadIdx.x;
    const int wid  = tid >> 5;
    const int lane = tid & 31;
    const int bid  = blockIdx.x;
    const int stride = gridDim.x;

    if (tid == 0) {
#pragma unroll
        for (int s = 0; s < DEPTH; s++) {
            MBARRIER_INIT(sb + SMEM_FULL  + 8 * s, 1);
            MBARRIER_INIT(sb + SMEM_EMPTY + 8 * s, 8);  // 8 compute warps
        }
    }

    // ---------------- Phase 1: quantize (all 288 threads) ----------------
    {
        const int total = ngx + ngw;
        const int npairs = (total + 1) >> 1;
        const int gtid = bid * NTHREADS + tid;
        const int gstr = stride * NTHREADS;
#pragma unroll 1
        for (int p = gtid; p < npairs; p += gstr) {
            int g0 = 2 * p;
#pragma unroll
            for (int j = 0; j < 2; j++) {
                int g = g0 + j;
                if (g < ngx)        quant_group(inp, g_qx, g);
                else if (g < total) quant_group(wgt, g_qw, g - ngx);
            }
        }
    }

    // ---------------- Grid barrier (ticket; wrap-safe; replay-safe) -------
    __threadfence();
    __syncthreads();
    if (tid == 0) {
        unsigned ticket = atomicAdd(&g_bar, 1u);
        unsigned target = ticket - (ticket % (unsigned)stride) + (unsigned)stride;
        unsigned cur;
        do {
            __nanosleep(128);
            cur = *(volatile unsigned*)&g_bar;
        } while ((int)(cur - target) < 0);
        __threadfence();
    }
    __syncthreads();

    // ---------------- Phase 2: GEMM ----------------
    if (wid == 8) {
        // TMA producer (persistent, ring continuous)
        if (lane == 0) {
            asm volatile("fence.proxy.async;" ::: "memory");
            int s = 0, wph = 0;
            int git = 0;
#pragma unroll 1
            for (int t = bid; t < NTILES; t += stride) {
                const int nt = t & 31;
                const int mt = t >> 5;
#pragma unroll 1
                for (int k = 0; k < NK; k++, git++) {
                    if (git >= DEPTH) MBARRIER_WAIT_PARITY(sb + SMEM_EMPTY + 8 * s, wph);
                    uint32_t fb = sb + SMEM_FULL + 8 * s;
                    MBARRIER_EXPECT_TX(fb, STAGE_BYTES);
                    uint32_t aDst = sb + SMEM_A0 + s * STAGE_A;
                    uint32_t bDst = sb + SMEM_B0 + s * STAGE_B;
                    tma_load_2d(aDst,       (const void*)&tma_a, k * BK,      mt * BM, fb);
                    tma_load_2d(aDst + SUB, (const void*)&tma_a, k * BK + 64, mt * BM, fb);
                    tma_load_2d(bDst,       (const void*)&tma_b, k * BK,      nt * BN, fb);
                    tma_load_2d(bDst + SUB, (const void*)&tma_b, k * BK + 64, nt * BN, fb);
                    if (++s == DEPTH) { s = 0; if (git >= DEPTH) wph ^= 1; }
                }
            }
        }
        return;
    }

    // Compute warps: 2x4 grid, 64x32 tiles
    const int wm = wid & 1;            // 2 warps along M
    const int wn = wid >> 1;           // 4 warps along N
    const int Mbase = wm * 64;
    const int Nbase = wn * 32;

    uint32_t aRow = (uint32_t)(Mbase + (lane & 15)) * 128 + ((lane >> 4) & 1) * 16;
    uint32_t bRow = (uint32_t)(Nbase + ((lane >> 4) << 3) + (lane & 7)) * 128
                  + ((lane >> 3) & 1) * 16;

    uint32_t aF[2][4][4];
    uint32_t bF[2][2][4];

    // Prologue: wait stage 0 of the first tile, preload kst0 into buffer 0.
    int s = 0, ph = 0;
    MBARRIER_WAIT_PARITY(sb + SMEM_FULL, 0);
    {
        uint32_t sA = sb + SMEM_A0;
        uint32_t sB = sb + SMEM_B0;
#pragma unroll
        for (int mi = 0; mi < 4; mi++)
            ldsm_x4(aF[0][mi], sA + sw128(aRow + (uint32_t)mi * 2048));
#pragma unroll
        for (int pi = 0; pi < 2; pi++)
            ldsm_x4(bF[0][pi], sB + sw128(bRow + (uint32_t)pi * 2048));
    }

#pragma unroll 1
    for (int t = bid; t < NTILES; t += stride) {
        const int nt = t & 31;
        const int mt = t >> 5;
        const bool last_tile = (t + stride >= NTILES);

        const int col0 = nt * BN + Nbase + 2 * (lane & 3);
        float2 bv[4];
#pragma unroll
        for (int ni = 0; ni < 4; ni++)
            bv[ni] = __ldg((const float2*)(bias + col0 + ni * 8));

        float acc[4][4][4];
#pragma unroll
        for (int mi = 0; mi < 4; mi++)
#pragma unroll
            for (int ni = 0; ni < 4; ni++)
#pragma unroll
                for (int j = 0; j < 4; j++) acc[mi][ni][j] = 0.f;

#pragma unroll 1
        for (int k = 0; k < NK; k++) {
            uint32_t sA = sb + SMEM_A0 + s * STAGE_A;
            uint32_t sB = sb + SMEM_B0 + s * STAGE_B;
#pragma unroll
            for (int kst = 0; kst < 8; kst++) {
                const int cur = kst & 1;
                const int nx  = cur ^ 1;
                if (kst < 7) {
                    const uint32_t hofs = (uint32_t)(((kst + 1) >> 2) * SUB);
                    const uint32_t kin  = (uint32_t)(((kst + 1) & 3) * 32);
#pragma unroll
                    for (int mi = 0; mi < 4; mi++)
                        ldsm_x4(aF[nx][mi], sA + hofs + sw128(aRow + (uint32_t)mi * 2048 + kin));
#pragma unroll
                    for (int pi = 0; pi < 2; pi++)
                        ldsm_x4(bF[nx][pi], sB + hofs + sw128(bRow + (uint32_t)pi * 2048 + kin));
                } else {
                    if (lane == 0) MBARRIER_ARRIVE(sb + SMEM_EMPTY + 8 * s);
                    if (!(last_tile && k == NK - 1)) {
                        const int sN  = (s + 1 == DEPTH) ? 0 : s + 1;
                        const int phN = (s + 1 == DEPTH) ? (ph ^ 1) : ph;
                        MBARRIER_WAIT_PARITY(sb + SMEM_FULL + 8 * sN, phN);
                        uint32_t sAN = sb + SMEM_A0 + sN * STAGE_A;
                        uint32_t sBN = sb + SMEM_B0 + sN * STAGE_B;
#pragma unroll
                        for (int mi = 0; mi < 4; mi++)
                            ldsm_x4(aF[nx][mi], sAN + sw128(aRow + (uint32_t)mi * 2048));
#pragma unroll
                        for (int pi = 0; pi < 2; pi++)
                            ldsm_x4(bF[nx][pi], sBN + sw128(bRow + (uint32_t)pi * 2048));
                        s = sN; ph = phN;
                    }
                }
#pragma unroll
                for (int mi = 0; mi < 4; mi++) {
#pragma unroll
                    for (int pi = 0; pi < 2; pi++) {
                        mma16816(acc[mi][2 * pi],     aF[cur][mi], bF[cur][pi][0], bF[cur][pi][1]);
                        mma16816(acc[mi][2 * pi + 1], aF[cur][mi], bF[cur][pi][2], bF[cur][pi][3]);
                    }
                }
            }
        }

        // Epilogue (producer prefetches next tile meanwhile)
        {
            const int row0 = mt * BM + Mbase + (lane >> 2);
#pragma unroll
            for (int ni = 0; ni < 4; ni++) {
                const int col = col0 + ni * 8;
#pragma unroll
                for (int mi = 0; mi < 4; mi++) {
                    const int r = row0 + mi * 16;
                    float2 v0 = make_float2(acc[mi][ni][0] + bv[ni].x, acc[mi][ni][1] + bv[ni].y);
                    float2 v1 = make_float2(acc[mi][ni][2] + bv[ni].x, acc[mi][ni][3] + bv[ni].y);
                    *reinterpret_cast<float2*>(out + (size_t)r * NDIM + col) = v0;
                    *reinterpret_cast<float2*>(out + (size_t)(r + 8) * NDIM + col) = v1;
                }
            }
        }
    }
}

// ============================================================
// Host launcher
// ============================================================
typedef CUresult (*tmap_encode_fn)(
    CUtensorMap*, CUtensorMapDataType, cuuint32_t, void*,
    const cuuint64_t*, const cuuint64_t*, const cuuint32_t*, const cuuint32_t*,
    CUtensorMapInterleave, CUtensorMapSwizzle, CUtensorMapL2promotion,
    CUtensorMapFloatOOBfill);

extern "C" void kernel_launch(void* const* d_in, const int* in_sizes, int n_in,
                              void* d_out, int out_size)
{
    const float* inp  = (const float*)d_in[0];
    const float* wgt  = (const float*)d_in[1];
    const float* bias = (const float*)d_in[2];
    float* out = (float*)d_out;

    const int M = in_sizes[0] / KDIM;  // 16384
    const int N = in_sizes[1] / KDIM;  // 4096
    const int ngx = M * (KDIM / GROUP);
    const int ngw = N * (KDIM / GROUP);

    void *qx_ptr = nullptr, *qw_ptr = nullptr;
    cudaGetSymbolAddress(&qx_ptr, g_qx);
    cudaGetSymbolAddress(&qw_ptr, g_qw);

    // Persistent grid = #SMs (152 on GB300)
    int nsm = 148;
    {
        int v = 0, dev = 0;
        cudaGetDevice(&dev);
        if (cudaDeviceGetAttribute(&v, cudaDevAttrMultiProcessorCount, dev)
                == cudaSuccess && v > 0)
            nsm = v;
    }

    // -------- tensor maps (host-side, capture-safe) --------
    tmap_encode_fn encode = nullptr;
    {
        cudaDriverEntryPointQueryResult qres;
        void* fn = nullptr;
        if (cudaGetDriverEntryPointByVersion("cuTensorMapEncodeTiled", &fn, 12000,
                                             cudaEnableDefault, &qres) != cudaSuccess ||
            fn == nullptr) {
            cudaGetDriverEntryPoint("cuTensorMapEncodeTiled", &fn,
                                    cudaEnableDefault, &qres);
        }
        encode = (tmap_encode_fn)fn;
    }

    CUtensorMap mapA, mapB;
    {
        cuuint64_t dims[2]    = {(cuuint64_t)KDIM, (cuuint64_t)M};
        cuuint64_t strides[1] = {(cuuint64_t)KDIM * sizeof(__nv_bfloat16)};
        cuuint32_t box[2]     = {64, BM};   // 64 bf16 = 128 B rows (SW128 limit)
        cuuint32_t es[2]      = {1, 1};
        encode(&mapA, CU_TENSOR_MAP_DATA_TYPE_BFLOAT16, 2, qx_ptr,
               dims, strides, box, es,
               CU_TENSOR_MAP_INTERLEAVE_NONE, CU_TENSOR_MAP_SWIZZLE_128B,
               CU_TENSOR_MAP_L2_PROMOTION_L2_128B, CU_TENSOR_MAP_FLOAT_OOB_FILL_NONE);
    }
    {
        cuuint64_t dims[2]    = {(cuuint64_t)KDIM, (cuuint64_t)N};
        cuuint64_t strides[1] = {(cuuint64_t)KDIM * sizeof(__nv_bfloat16)};
        cuuint32_t box[2]     = {64, BN};
        cuuint32_t es[2]      = {1, 1};
        encode(&mapB, CU_TENSOR_MAP_DATA_TYPE_BFLOAT16, 2, qw_ptr,
               dims, strides, box, es,
               CU_TENSOR_MAP_INTERLEAVE_NONE, CU_TENSOR_MAP_SWIZZLE_128B,
               CU_TENSOR_MAP_L2_PROMOTION_L2_128B, CU_TENSOR_MAP_FLOAT_OOB_FILL_NONE);
    }

    // -------- Fused quant + GEMM (persistent, 1 CTA/SM on ALL SMs) --------
    cudaFuncSetAttribute(bfp_fused_kernel,
                         cudaFuncAttributeMaxDynamicSharedMemorySize, SMEM_TOTAL);
    bfp_fused_kernel<<<nsm, NTHREADS, SMEM_TOTAL>>>(mapA, mapB, inp, wgt,
                                                    bias, out, ngx, ngw);
}

// round 15
// speedup vs baseline: 1.0207x; 1.0207x over previous
#include <cuda_runtime.h>
#include <cuda.h>
#include <cuda_bf16.h>
#include <cstdint>

// ============================================================
// Problem constants
// ============================================================
#define KDIM 4096
#define NDIM 4096
#define GROUP 16

#define BM 128
#define BN 128
#define BK 128                   // per stage (two 64-col SW128 sub-tiles)
#define DEPTH 3
#define NK (KDIM / BK)           // 32 k-iterations per tile
#define NTHREADS 288             // 8 compute warps + 1 producer warp
#define NTILES 4096              // (16384/128) * (4096/128)

// ============================================================
// Scratch (device globals: allocation-free rule)
// ============================================================
__device__ __align__(256) __nv_bfloat16 g_qx[(size_t)16384 * KDIM]; // 128 MB
__device__ __align__(256) __nv_bfloat16 g_qw[(size_t)NDIM * KDIM];  //  32 MB

// ============================================================
// PTX helpers (baseline PTX — toolchain targets sm_103, no tcgen05)
// ============================================================
__device__ __forceinline__ uint32_t smem_to_u32(const void* smem_ptr) {
    uint32_t addr;
    asm("{ .reg .u64 tmp; cvta.to.shared.u64 tmp, %1; cvt.u32.u64 %0, tmp; }"
        : "=r"(addr) : "l"(smem_ptr));
    return addr;
}

#define MBARRIER_INIT(mbar, count) \
    asm volatile("mbarrier.init.shared.b64 [%0], %1;" \
        :: "r"((uint32_t)(mbar)), "r"((uint32_t)(count)) : "memory")

#define MBARRIER_EXPECT_TX(mbar, tx_bytes) \
    asm volatile("mbarrier.arrive.expect_tx.shared.b64 _, [%0], %1;" \
        :: "r"((uint32_t)(mbar)), "r"((uint32_t)(tx_bytes)) : "memory")

#define MBARRIER_ARRIVE(mbar) \
    asm volatile("mbarrier.arrive.shared.b64 _, [%0];" \
        :: "r"((uint32_t)(mbar)) : "memory")

#define MBARRIER_WAIT_PARITY(mbar, parity) do { \
    uint32_t _m = (uint32_t)(mbar); \
    uint32_t _p = (uint32_t)(parity); \
    uint32_t _done; \
    asm volatile( \
        "{\n\t.reg .pred p;\n\t" \
        "mbarrier.try_wait.parity.acquire.cta.shared::cta.b64 p, [%1], %2;\n\t" \
        "selp.b32 %0, 1, 0, p;\n\t}" \
        : "=r"(_done) : "r"(_m), "r"(_p) : "memory"); \
    if (!_done) { \
        asm volatile( \
            "{\n\t.reg .pred P1;\n\t" \
            "WAIT_LOOP_%=:\n\t" \
            "mbarrier.try_wait.parity.acquire.cta.shared::cta.b64 P1, [%0], %1, 0x989680;\n\t" \
            "@P1 bra.uni WAIT_DONE_%=;\n\t" \
            "bra.uni WAIT_LOOP_%=;\n\t" \
            "WAIT_DONE_%=:\n\t}" \
            :: "r"(_m), "r"(_p) : "memory"); \
    } \
} while (0)

__device__ __forceinline__ void tma_load_2d(
    uint32_t smem_addr, const void* tensor_map,
    int32_t cx, int32_t cy, uint32_t mbar)
{
    asm volatile(
        "cp.async.bulk.tensor.2d.shared::cta.global.tile.mbarrier::complete_tx::bytes "
        "[%0], [%1, {%2, %3}], [%4];"
        :: "r"(smem_addr), "l"(tensor_map), "r"(cx), "r"(cy), "r"(mbar)
        : "memory");
}

// SW128 swizzle (matches TMA CU_TENSOR_MAP_SWIZZLE_128B)
__device__ __forceinline__ uint32_t sw128(uint32_t o) {
    return o ^ ((o >> 3) & 0x70);
}

__device__ __forceinline__ void ldsm_x4(uint32_t* r, uint32_t addr) {
    asm volatile(
        "ldmatrix.sync.aligned.m8n8.x4.shared.b16 {%0,%1,%2,%3}, [%4];"
        : "=r"(r[0]), "=r"(r[1]), "=r"(r[2]), "=r"(r[3]) : "r"(addr));
}

__device__ __forceinline__ void mma16816(float* c, const uint32_t* a,
                                         uint32_t b0, uint32_t b1) {
    asm volatile(
        "mma.sync.aligned.m16n8k16.row.col.f32.bf16.bf16.f32 "
        "{%0,%1,%2,%3}, {%4,%5,%6,%7}, {%8,%9}, {%0,%1,%2,%3};"
        : "+f"(c[0]), "+f"(c[1]), "+f"(c[2]), "+f"(c[3])
        : "r"(a[0]), "r"(a[1]), "r"(a[2]), "r"(a[3]), "r"(b0), "r"(b1));
}

// ============================================================
// Fused BFP quantize, MLP-optimized: each thread handles a PAIR of
// adjacent groups (128 B contiguous). All 8 LDG.128 issue up-front
// (MLP=8) with evict-first (.cs) since inputs are never re-read.
// ngx is even, so a pair never straddles the X/W boundary.
// ============================================================
__device__ __forceinline__ void quant_group_regs(const float4& f0, const float4& f1,
                                                 const float4& f2, const float4& f3,
                                                 uint4* dst)
{
    float v[GROUP] = {f0.x, f0.y, f0.z, f0.w, f1.x, f1.y, f1.z, f1.w,
                      f2.x, f2.y, f2.z, f2.w, f3.x, f3.y, f3.z, f3.w};
    float m = 0.f;
#pragma unroll
    for (int i = 0; i < GROUP; i++) m = fmaxf(m, fabsf(v[i]));

    union { __nv_bfloat16 h[GROUP]; uint4 u[2]; } pk;
    if (m > 0.f) {
        unsigned e = __float_as_uint(m) >> 23;   // biased exp = 127+floor(log2 m)
        if (e < 8u) e = 8u;
        float scale = __uint_as_float((e - 7u) << 23);     // 2^(exp-7)
        float inv   = __uint_as_float((261u - e) << 23);   // 2^(7-exp) exact
#pragma unroll
        for (int i = 0; i < GROUP; i++) {
            float r = rintf(v[i] * inv);                   // round-half-even
            r = fminf(127.f, fmaxf(-127.f, r));
            pk.h[i] = __float2bfloat16(r * scale);         // exact in bf16
        }
    } else {
#pragma unroll
        for (int i = 0; i < GROUP; i++) pk.h[i] = __float2bfloat16(0.f);
    }
    dst[0] = pk.u[0];
    dst[1] = pk.u[1];
}

__global__ void bfp_quant_fused_kernel(const float* __restrict__ x,
                                       __nv_bfloat16* __restrict__ qx,
                                       int ngx,
                                       const float* __restrict__ w,
                                       __nv_bfloat16* __restrict__ qw,
                                       int ngw)
{
    int p = blockIdx.x * blockDim.x + threadIdx.x;   // pair index
    int g0 = 2 * p;                                   // first group of pair
    const float* src_base;
    __nv_bfloat16* dst_base;
    if (g0 < ngx) {
        src_base = x; dst_base = qx;
    } else {
        g0 -= ngx;
        if (g0 >= ngw) return;
        src_base = w; dst_base = qw;
    }

    const float4* src = reinterpret_cast<const float4*>(src_base + (size_t)g0 * GROUP);
    float4 r[8];
#pragma unroll
    for (int i = 0; i < 8; i++) r[i] = __ldcs(src + i);   // 8 LDG.128 in flight

    uint4 outp[4];
    quant_group_regs(r[0], r[1], r[2], r[3], outp);
    quant_group_regs(r[4], r[5], r[6], r[7], outp + 2);

    uint4* dst = reinterpret_cast<uint4*>(dst_base + (size_t)g0 * GROUP);
#pragma unroll
    for (int i = 0; i < 4; i++) dst[i] = outp[i];
}

// ============================================================
// Persistent GEMM: out[16384,4096] = qx @ qw^T + bias
// grid = #SMs (152 on GB300). Ring (DEPTH=3 x 64 KB) phase-continuous
// across tiles. Consumer: fragment double-buffer + cross-stage/cross-tile
// pipelining. (Round-11 proven body, unchanged.)
// ============================================================
static constexpr int SMEM_FULL  = 0;
static constexpr int SMEM_EMPTY = SMEM_FULL + 8 * DEPTH;
static constexpr int SUB      = 16384;                      // 128x64 bf16 sub-tile
static constexpr int STAGE_A  = 2 * SUB;                    // 32768 B
static constexpr int STAGE_B  = 2 * SUB;                    // 32768 B
static constexpr int SMEM_A0  = 1024;
static constexpr int SMEM_B0  = SMEM_A0 + DEPTH * STAGE_A;  // 99328
static constexpr int SMEM_TOTAL = SMEM_B0 + DEPTH * STAGE_B; // 197632
static constexpr unsigned STAGE_BYTES = (unsigned)(STAGE_A + STAGE_B); // 65536

__global__ void __launch_bounds__(NTHREADS, 1) bfp_gemm_kernel(
    const __grid_constant__ CUtensorMap tma_a,
    const __grid_constant__ CUtensorMap tma_b,
    const float* __restrict__ bias,
    float* __restrict__ out)
{
    extern __shared__ char smem[];
    uint32_t sb = smem_to_u32(smem);
    const int tid  = threadIdx.x;
    const int wid  = tid >> 5;
    const int lane = tid & 31;
    const int bid  = blockIdx.x;
    const int stride = gridDim.x;

    if (tid == 0) {
#pragma unroll
        for (int s = 0; s < DEPTH; s++) {
            MBARRIER_INIT(sb + SMEM_FULL  + 8 * s, 1);
            MBARRIER_INIT(sb + SMEM_EMPTY + 8 * s, 8);  // 8 compute warps
        }
    }
    __syncthreads();

    if (wid == 8) {
        // ---------------- TMA producer (persistent, ring continuous) -------
        if (lane == 0) {
            int s = 0, wph = 0;
            int git = 0;
#pragma unroll 1
            for (int t = bid; t < NTILES; t += stride) {
                const int nt = t & 31;
                const int mt = t >> 5;
#pragma unroll 1
                for (int k = 0; k < NK; k++, git++) {
                    if (git >= DEPTH) MBARRIER_WAIT_PARITY(sb + SMEM_EMPTY + 8 * s, wph);
                    uint32_t fb = sb + SMEM_FULL + 8 * s;
                    MBARRIER_EXPECT_TX(fb, STAGE_BYTES);
                    uint32_t aDst = sb + SMEM_A0 + s * STAGE_A;
                    uint32_t bDst = sb + SMEM_B0 + s * STAGE_B;
                    tma_load_2d(aDst,       (const void*)&tma_a, k * BK,      mt * BM, fb);
                    tma_load_2d(aDst + SUB, (const void*)&tma_a, k * BK + 64, mt * BM, fb);
                    tma_load_2d(bDst,       (const void*)&tma_b, k * BK,      nt * BN, fb);
                    tma_load_2d(bDst + SUB, (const void*)&tma_b, k * BK + 64, nt * BN, fb);
                    if (++s == DEPTH) { s = 0; if (git >= DEPTH) wph ^= 1; }
                }
            }
        }
        return;
    }

    // ---------------- Compute warps: 2x4 grid, 64x32 tiles ----------------
    const int wm = wid & 1;            // 2 warps along M
    const int wn = wid >> 1;           // 4 warps along N
    const int Mbase = wm * 64;
    const int Nbase = wn * 32;

    // ldmatrix lane addresses (byte offsets within one 64-col sub-tile;
    // rows are 128 B wide)
    uint32_t aRow = (uint32_t)(Mbase + (lane & 15)) * 128 + ((lane >> 4) & 1) * 16;
    uint32_t bRow = (uint32_t)(Nbase + ((lane >> 4) << 3) + (lane & 7)) * 128
                  + ((lane >> 3) & 1) * 16;

    uint32_t aF[2][4][4];
    uint32_t bF[2][2][4];

    // Prologue: wait stage 0 of the first tile, preload kst0 into buffer 0.
    int s = 0, ph = 0;
    MBARRIER_WAIT_PARITY(sb + SMEM_FULL, 0);
    {
        uint32_t sA = sb + SMEM_A0;
        uint32_t sB = sb + SMEM_B0;
#pragma unroll
        for (int mi = 0; mi < 4; mi++)
            ldsm_x4(aF[0][mi], sA + sw128(aRow + (uint32_t)mi * 2048));
#pragma unroll
        for (int pi = 0; pi < 2; pi++)
            ldsm_x4(bF[0][pi], sB + sw128(bRow + (uint32_t)pi * 2048));
    }

#pragma unroll 1
    for (int t = bid; t < NTILES; t += stride) {
        const int nt = t & 31;
        const int mt = t >> 5;
        const bool last_tile = (t + stride >= NTILES);

        const int col0 = nt * BN + Nbase + 2 * (lane & 3);
        float2 bv[4];
#pragma unroll
        for (int ni = 0; ni < 4; ni++)
            bv[ni] = __ldg((const float2*)(bias + col0 + ni * 8));

        float acc[4][4][4];
#pragma unroll
        for (int mi = 0; mi < 4; mi++)
#pragma unroll
            for (int ni = 0; ni < 4; ni++)
#pragma unroll
                for (int j = 0; j < 4; j++) acc[mi][ni][j] = 0.f;

#pragma unroll 1
        for (int k = 0; k < NK; k++) {
            uint32_t sA = sb + SMEM_A0 + s * STAGE_A;
            uint32_t sB = sb + SMEM_B0 + s * STAGE_B;
#pragma unroll
            for (int kst = 0; kst < 8; kst++) {
                const int cur = kst & 1;
                const int nx  = cur ^ 1;
                if (kst < 7) {
                    // preload next kst of the SAME stage
                    const uint32_t hofs = (uint32_t)(((kst + 1) >> 2) * SUB);
                    const uint32_t kin  = (uint32_t)(((kst + 1) & 3) * 32);
#pragma unroll
                    for (int mi = 0; mi < 4; mi++)
                        ldsm_x4(aF[nx][mi], sA + hofs + sw128(aRow + (uint32_t)mi * 2048 + kin));
#pragma unroll
                    for (int pi = 0; pi < 2; pi++)
                        ldsm_x4(bF[nx][pi], sB + hofs + sw128(bRow + (uint32_t)pi * 2048 + kin));
                } else {
                    // all LDSMs of stage s issued: release buffer, then wait
                    // for the NEXT stage (possibly of the next tile) and
                    // preload its kst0 before the tail MMAs of this stage.
                    if (lane == 0) MBARRIER_ARRIVE(sb + SMEM_EMPTY + 8 * s);
                    if (!(last_tile && k == NK - 1)) {
                        const int sN  = (s + 1 == DEPTH) ? 0 : s + 1;
                        const int phN = (s + 1 == DEPTH) ? (ph ^ 1) : ph;
                        MBARRIER_WAIT_PARITY(sb + SMEM_FULL + 8 * sN, phN);
                        uint32_t sAN = sb + SMEM_A0 + sN * STAGE_A;
                        uint32_t sBN = sb + SMEM_B0 + sN * STAGE_B;
#pragma unroll
                        for (int mi = 0; mi < 4; mi++)
                            ldsm_x4(aF[nx][mi], sAN + sw128(aRow + (uint32_t)mi * 2048));
#pragma unroll
                        for (int pi = 0; pi < 2; pi++)
                            ldsm_x4(bF[nx][pi], sBN + sw128(bRow + (uint32_t)pi * 2048));
                        s = sN; ph = phN;
                    }
                }
#pragma unroll
                for (int mi = 0; mi < 4; mi++) {
#pragma unroll
                    for (int pi = 0; pi < 2; pi++) {
                        mma16816(acc[mi][2 * pi],     aF[cur][mi], bF[cur][pi][0], bF[cur][pi][1]);
                        mma16816(acc[mi][2 * pi + 1], aF[cur][mi], bF[cur][pi][2], bF[cur][pi][3]);
                    }
                }
            }
        }

        // -------- Epilogue (producer prefetches next tile meanwhile) -------
        {
            const int row0 = mt * BM + Mbase + (lane >> 2);
#pragma unroll
            for (int ni = 0; ni < 4; ni++) {
                const int col = col0 + ni * 8;
#pragma unroll
                for (int mi = 0; mi < 4; mi++) {
                    const int r = row0 + mi * 16;
                    float2 v0 = make_float2(acc[mi][ni][0] + bv[ni].x, acc[mi][ni][1] + bv[ni].y);
                    float2 v1 = make_float2(acc[mi][ni][2] + bv[ni].x, acc[mi][ni][3] + bv[ni].y);
                    *reinterpret_cast<float2*>(out + (size_t)r * NDIM + col) = v0;
                    *reinterpret_cast<float2*>(out + (size_t)(r + 8) * NDIM + col) = v1;
                }
            }
        }
    }
}

// ============================================================
// Host launcher
// ============================================================
typedef CUresult (*tmap_encode_fn)(
    CUtensorMap*, CUtensorMapDataType, cuuint32_t, void*,
    const cuuint64_t*, const cuuint64_t*, const cuuint32_t*, const cuuint32_t*,
    CUtensorMapInterleave, CUtensorMapSwizzle, CUtensorMapL2promotion,
    CUtensorMapFloatOOBfill);

extern "C" void kernel_launch(void* const* d_in, const int* in_sizes, int n_in,
                              void* d_out, int out_size)
{
    const float* inp  = (const float*)d_in[0];
    const float* wgt  = (const float*)d_in[1];
    const float* bias = (const float*)d_in[2];
    float* out = (float*)d_out;

    const int M = in_sizes[0] / KDIM;  // 16384
    const int N = in_sizes[1] / KDIM;  // 4096

    void *qx_ptr = nullptr, *qw_ptr = nullptr;
    cudaGetSymbolAddress(&qx_ptr, g_qx);
    cudaGetSymbolAddress(&qw_ptr, g_qw);

    // Persistent grid = #SMs (152 on GB300; attribute query is capture-safe)
    int nsm = 148;
    {
        int v = 0, dev = 0;
        cudaGetDevice(&dev);
        if (cudaDeviceGetAttribute(&v, cudaDevAttrMultiProcessorCount, dev)
                == cudaSuccess && v > 0)
            nsm = v;
    }

    // -------- quantize both operands (one launch, pair-per-thread) --------
    {
        int gx = M * (KDIM / GROUP);           // even
        int gw = N * (KDIM / GROUP);
        int npairs = (gx + gw) / 2;
        bfp_quant_fused_kernel<<<(npairs + 255) / 256, 256>>>(
            inp, (__nv_bfloat16*)qx_ptr, gx,
            wgt, (__nv_bfloat16*)qw_ptr, gw);
    }

    // -------- tensor maps (host-side, capture-safe) --------
    tmap_encode_fn encode = nullptr;
    {
        cudaDriverEntryPointQueryResult qres;
        void* fn = nullptr;
        if (cudaGetDriverEntryPointByVersion("cuTensorMapEncodeTiled", &fn, 12000,
                                             cudaEnableDefault, &qres) != cudaSuccess ||
            fn == nullptr) {
            cudaGetDriverEntryPoint("cuTensorMapEncodeTiled", &fn,
                                    cudaEnableDefault, &qres);
        }
        encode = (tmap_encode_fn)fn;
    }

    CUtensorMap mapA, mapB;
    {
        cuuint64_t dims[2]    = {(cuuint64_t)KDIM, (cuuint64_t)M};
        cuuint64_t strides[1] = {(cuuint64_t)KDIM * sizeof(__nv_bfloat16)};
        cuuint32_t box[2]     = {64, BM};   // 64 bf16 = 128 B rows (SW128 limit)
        cuuint32_t es[2]      = {1, 1};
        encode(&mapA, CU_TENSOR_MAP_DATA_TYPE_BFLOAT16, 2, qx_ptr,
               dims, strides, box, es,
               CU_TENSOR_MAP_INTERLEAVE_NONE, CU_TENSOR_MAP_SWIZZLE_128B,
               CU_TENSOR_MAP_L2_PROMOTION_L2_128B, CU_TENSOR_MAP_FLOAT_OOB_FILL_NONE);
    }
    {
        cuuint64_t dims[2]    = {(cuuint64_t)KDIM, (cuuint64_t)N};
        cuuint64_t strides[1] = {(cuuint64_t)KDIM * sizeof(__nv_bfloat16)};
        cuuint32_t box[2]     = {64, BN};
        cuuint32_t es[2]      = {1, 1};
        encode(&mapB, CU_TENSOR_MAP_DATA_TYPE_BFLOAT16, 2, qw_ptr,
               dims, strides, box, es,
               CU_TENSOR_MAP_INTERLEAVE_NONE, CU_TENSOR_MAP_SWIZZLE_128B,
               CU_TENSOR_MAP_L2_PROMOTION_L2_128B, CU_TENSOR_MAP_FLOAT_OOB_FILL_NONE);
    }

    // -------- GEMM (persistent, 1 CTA/SM on ALL SMs) --------
    cudaFuncSetAttribute(bfp_gemm_kernel,
                         cudaFuncAttributeMaxDynamicSharedMemorySize, SMEM_TOTAL);
    bfp_gemm_kernel<<<nsm, NTHREADS, SMEM_TOTAL>>>(mapA, mapB, bias, out);
}

// round 16
// speedup vs baseline: 1.0422x; 1.0211x over previous
#include <cuda_runtime.h>
#include <cuda.h>
#include <cuda_bf16.h>
#include <cstdint>

// ============================================================
// Problem constants
// ============================================================
#define KDIM 4096
#define NDIM 4096
#define GROUP 16

#define BM 128
#define BN 128
#define BK 128                   // per stage (two 64-col SW128 sub-tiles)
#define DEPTH 3
#define NK (KDIM / BK)           // 32 k-iterations per tile
#define NTHREADS 288             // 8 compute warps + 1 producer warp
#define NTILES 4096              // (16384/128) * (4096/128)

// ============================================================
// Scratch (device globals: allocation-free rule)
// ============================================================
__device__ __align__(256) __nv_bfloat16 g_qx[(size_t)16384 * KDIM]; // 128 MB
__device__ __align__(256) __nv_bfloat16 g_qw[(size_t)NDIM * KDIM];  //  32 MB

// ============================================================
// PTX helpers (baseline PTX — toolchain targets sm_103, no tcgen05)
// ============================================================
__device__ __forceinline__ uint32_t smem_to_u32(const void* smem_ptr) {
    uint32_t addr;
    asm("{ .reg .u64 tmp; cvta.to.shared.u64 tmp, %1; cvt.u32.u64 %0, tmp; }"
        : "=r"(addr) : "l"(smem_ptr));
    return addr;
}

#define MBARRIER_INIT(mbar, count) \
    asm volatile("mbarrier.init.shared.b64 [%0], %1;" \
        :: "r"((uint32_t)(mbar)), "r"((uint32_t)(count)) : "memory")

#define MBARRIER_EXPECT_TX(mbar, tx_bytes) \
    asm volatile("mbarrier.arrive.expect_tx.shared.b64 _, [%0], %1;" \
        :: "r"((uint32_t)(mbar)), "r"((uint32_t)(tx_bytes)) : "memory")

#define MBARRIER_ARRIVE(mbar) \
    asm volatile("mbarrier.arrive.shared.b64 _, [%0];" \
        :: "r"((uint32_t)(mbar)) : "memory")

#define MBARRIER_WAIT_PARITY(mbar, parity) do { \
    uint32_t _m = (uint32_t)(mbar); \
    uint32_t _p = (uint32_t)(parity); \
    uint32_t _done; \
    asm volatile( \
        "{\n\t.reg .pred p;\n\t" \
        "mbarrier.try_wait.parity.acquire.cta.shared::cta.b64 p, [%1], %2;\n\t" \
        "selp.b32 %0, 1, 0, p;\n\t}" \
        : "=r"(_done) : "r"(_m), "r"(_p) : "memory"); \
    if (!_done) { \
        asm volatile( \
            "{\n\t.reg .pred P1;\n\t" \
            "WAIT_LOOP_%=:\n\t" \
            "mbarrier.try_wait.parity.acquire.cta.shared::cta.b64 P1, [%0], %1, 0x989680;\n\t" \
            "@P1 bra.uni WAIT_DONE_%=;\n\t" \
            "bra.uni WAIT_LOOP_%=;\n\t" \
            "WAIT_DONE_%=:\n\t}" \
            :: "r"(_m), "r"(_p) : "memory"); \
    } \
} while (0)

__device__ __forceinline__ void tma_load_2d(
    uint32_t smem_addr, const void* tensor_map,
    int32_t cx, int32_t cy, uint32_t mbar)
{
    asm volatile(
        "cp.async.bulk.tensor.2d.shared::cta.global.tile.mbarrier::complete_tx::bytes "
        "[%0], [%1, {%2, %3}], [%4];"
        :: "r"(smem_addr), "l"(tensor_map), "r"(cx), "r"(cy), "r"(mbar)
        : "memory");
}

// SW128 swizzle (matches TMA CU_TENSOR_MAP_SWIZZLE_128B)
__device__ __forceinline__ uint32_t sw128(uint32_t o) {
    return o ^ ((o >> 3) & 0x70);
}

__device__ __forceinline__ void ldsm_x4(uint32_t* r, uint32_t addr) {
    asm volatile(
        "ldmatrix.sync.aligned.m8n8.x4.shared.b16 {%0,%1,%2,%3}, [%4];"
        : "=r"(r[0]), "=r"(r[1]), "=r"(r[2]), "=r"(r[3]) : "r"(addr));
}

__device__ __forceinline__ void mma16816(float* c, const uint32_t* a,
                                         uint32_t b0, uint32_t b1) {
    asm volatile(
        "mma.sync.aligned.m16n8k16.row.col.f32.bf16.bf16.f32 "
        "{%0,%1,%2,%3}, {%4,%5,%6,%7}, {%8,%9}, {%0,%1,%2,%3};"
        : "+f"(c[0]), "+f"(c[1]), "+f"(c[2]), "+f"(c[3])
        : "r"(a[0]), "r"(a[1]), "r"(a[2]), "r"(a[3]), "r"(b0), "r"(b1));
}

// ============================================================
// Fused BFP quantize: both tensors in one launch (round-11 proven
// version: one group of 16 per thread — measured at DRAM roofline).
// Ends with griddepcontrol.launch_dependents so the PDL-launched GEMM
// can begin its launch/setup during this kernel's tail drain.
// ============================================================
__global__ void bfp_quant_fused_kernel(const float* __restrict__ x,
                                       __nv_bfloat16* __restrict__ qx,
                                       int ngx,
                                       const float* __restrict__ w,
                                       __nv_bfloat16* __restrict__ qw,
                                       int ngw)
{
    int g = blockIdx.x * blockDim.x + threadIdx.x;
    const float* src_base;
    __nv_bfloat16* dst_base;
    bool active = true;
    if (g < ngx) {
        src_base = x; dst_base = qx;
    } else {
        g -= ngx;
        if (g >= ngw) active = false;
        src_base = w; dst_base = qw;
    }
    if (active) {
        const float4* src = reinterpret_cast<const float4*>(src_base + (size_t)g * GROUP);
        float4 f0 = src[0], f1 = src[1], f2 = src[2], f3 = src[3];
        float v[GROUP] = {f0.x, f0.y, f0.z, f0.w, f1.x, f1.y, f1.z, f1.w,
                          f2.x, f2.y, f2.z, f2.w, f3.x, f3.y, f3.z, f3.w};
        float m = 0.f;
#pragma unroll
        for (int i = 0; i < GROUP; i++) m = fmaxf(m, fabsf(v[i]));

        union { __nv_bfloat16 h[GROUP]; uint4 u[2]; } pk;
        if (m > 0.f) {
            unsigned e = __float_as_uint(m) >> 23;   // biased exp = 127+floor(log2 m)
            if (e < 8u) e = 8u;
            float scale = __uint_as_float((e - 7u) << 23);     // 2^(exp-7)
            float inv   = __uint_as_float((261u - e) << 23);   // 2^(7-exp) exact
#pragma unroll
            for (int i = 0; i < GROUP; i++) {
                float r = rintf(v[i] * inv);                   // round-half-even
                r = fminf(127.f, fmaxf(-127.f, r));
                pk.h[i] = __float2bfloat16(r * scale);         // exact in bf16
            }
        } else {
#pragma unroll
            for (int i = 0; i < GROUP; i++) pk.h[i] = __float2bfloat16(0.f);
        }
        uint4* dst = reinterpret_cast<uint4*>(dst_base + (size_t)g * GROUP);
        dst[0] = pk.u[0];
        dst[1] = pk.u[1];
    }
    // Allow the dependent (GEMM) grid to start launching.
    asm volatile("griddepcontrol.launch_dependents;" ::: "memory");
}

// ============================================================
// Persistent GEMM: out[16384,4096] = qx @ qw^T + bias
// grid = #SMs (152 on GB300). Ring (DEPTH=3 x 64 KB) phase-continuous
// across tiles. Consumer: fragment double-buffer + cross-stage/cross-tile
// pipelining. (Round-11 proven body; only addition: griddepcontrol.wait
// in the producer before the first TMA, enabling PDL overlap.)
// ============================================================
static constexpr int SMEM_FULL  = 0;
static constexpr int SMEM_EMPTY = SMEM_FULL + 8 * DEPTH;
static constexpr int SUB      = 16384;                      // 128x64 bf16 sub-tile
static constexpr int STAGE_A  = 2 * SUB;                    // 32768 B
static constexpr int STAGE_B  = 2 * SUB;                    // 32768 B
static constexpr int SMEM_A0  = 1024;
static constexpr int SMEM_B0  = SMEM_A0 + DEPTH * STAGE_A;  // 99328
static constexpr int SMEM_TOTAL = SMEM_B0 + DEPTH * STAGE_B; // 197632
static constexpr unsigned STAGE_BYTES = (unsigned)(STAGE_A + STAGE_B); // 65536

__global__ void __launch_bounds__(NTHREADS, 1) bfp_gemm_kernel(
    const __grid_constant__ CUtensorMap tma_a,
    const __grid_constant__ CUtensorMap tma_b,
    const float* __restrict__ bias,
    float* __restrict__ out)
{
    extern __shared__ char smem[];
    uint32_t sb = smem_to_u32(smem);
    const int tid  = threadIdx.x;
    const int wid  = tid >> 5;
    const int lane = tid & 31;
    const int bid  = blockIdx.x;
    const int stride = gridDim.x;

    if (tid == 0) {
#pragma unroll
        for (int s = 0; s < DEPTH; s++) {
            MBARRIER_INIT(sb + SMEM_FULL  + 8 * s, 1);
            MBARRIER_INIT(sb + SMEM_EMPTY + 8 * s, 8);  // 8 compute warps
        }
    }
    __syncthreads();

    if (wid == 8) {
        // ---------------- TMA producer (persistent, ring continuous) -------
        if (lane == 0) {
            // PDL: block until the quant kernel's stores are visible, THEN
            // start the TMA ring. All setup above overlapped quant execution.
            asm volatile("griddepcontrol.wait;" ::: "memory");
            asm volatile("fence.proxy.async;" ::: "memory");
            int s = 0, wph = 0;
            int git = 0;
#pragma unroll 1
            for (int t = bid; t < NTILES; t += stride) {
                const int nt = t & 31;
                const int mt = t >> 5;
#pragma unroll 1
                for (int k = 0; k < NK; k++, git++) {
                    if (git >= DEPTH) MBARRIER_WAIT_PARITY(sb + SMEM_EMPTY + 8 * s, wph);
                    uint32_t fb = sb + SMEM_FULL + 8 * s;
                    MBARRIER_EXPECT_TX(fb, STAGE_BYTES);
                    uint32_t aDst = sb + SMEM_A0 + s * STAGE_A;
                    uint32_t bDst = sb + SMEM_B0 + s * STAGE_B;
                    tma_load_2d(aDst,       (const void*)&tma_a, k * BK,      mt * BM, fb);
                    tma_load_2d(aDst + SUB, (const void*)&tma_a, k * BK + 64, mt * BM, fb);
                    tma_load_2d(bDst,       (const void*)&tma_b, k * BK,      nt * BN, fb);
                    tma_load_2d(bDst + SUB, (const void*)&tma_b, k * BK + 64, nt * BN, fb);
                    if (++s == DEPTH) { s = 0; if (git >= DEPTH) wph ^= 1; }
                }
            }
        }
        return;
    }

    // ---------------- Compute warps: 2x4 grid, 64x32 tiles ----------------
    const int wm = wid & 1;            // 2 warps along M
    const int wn = wid >> 1;           // 4 warps along N
    const int Mbase = wm * 64;
    const int Nbase = wn * 32;

    // ldmatrix lane addresses (byte offsets within one 64-col sub-tile;
    // rows are 128 B wide)
    uint32_t aRow = (uint32_t)(Mbase + (lane & 15)) * 128 + ((lane >> 4) & 1) * 16;
    uint32_t bRow = (uint32_t)(Nbase + ((lane >> 4) << 3) + (lane & 7)) * 128
                  + ((lane >> 3) & 1) * 16;

    uint32_t aF[2][4][4];
    uint32_t bF[2][2][4];

    // Prologue: wait stage 0 of the first tile, preload kst0 into buffer 0.
    int s = 0, ph = 0;
    MBARRIER_WAIT_PARITY(sb + SMEM_FULL, 0);
    {
        uint32_t sA = sb + SMEM_A0;
        uint32_t sB = sb + SMEM_B0;
#pragma unroll
        for (int mi = 0; mi < 4; mi++)
            ldsm_x4(aF[0][mi], sA + sw128(aRow + (uint32_t)mi * 2048));
#pragma unroll
        for (int pi = 0; pi < 2; pi++)
            ldsm_x4(bF[0][pi], sB + sw128(bRow + (uint32_t)pi * 2048));
    }

#pragma unroll 1
    for (int t = bid; t < NTILES; t += stride) {
        const int nt = t & 31;
        const int mt = t >> 5;
        const bool last_tile = (t + stride >= NTILES);

        const int col0 = nt * BN + Nbase + 2 * (lane & 3);
        float2 bv[4];
#pragma unroll
        for (int ni = 0; ni < 4; ni++)
            bv[ni] = __ldg((const float2*)(bias + col0 + ni * 8));

        float acc[4][4][4];
#pragma unroll
        for (int mi = 0; mi < 4; mi++)
#pragma unroll
            for (int ni = 0; ni < 4; ni++)
#pragma unroll
                for (int j = 0; j < 4; j++) acc[mi][ni][j] = 0.f;

#pragma unroll 1
        for (int k = 0; k < NK; k++) {
            uint32_t sA = sb + SMEM_A0 + s * STAGE_A;
            uint32_t sB = sb + SMEM_B0 + s * STAGE_B;
#pragma unroll
            for (int kst = 0; kst < 8; kst++) {
                const int cur = kst & 1;
                const int nx  = cur ^ 1;
                if (kst < 7) {
                    // preload next kst of the SAME stage
                    const uint32_t hofs = (uint32_t)(((kst + 1) >> 2) * SUB);
                    const uint32_t kin  = (uint32_t)(((kst + 1) & 3) * 32);
#pragma unroll
                    for (int mi = 0; mi < 4; mi++)
                        ldsm_x4(aF[nx][mi], sA + hofs + sw128(aRow + (uint32_t)mi * 2048 + kin));
#pragma unroll
                    for (int pi = 0; pi < 2; pi++)
                        ldsm_x4(bF[nx][pi], sB + hofs + sw128(bRow + (uint32_t)pi * 2048 + kin));
                } else {
                    // all LDSMs of stage s issued: release buffer, then wait
                    // for the NEXT stage (possibly of the next tile) and
                    // preload its kst0 before the tail MMAs of this stage.
                    if (lane == 0) MBARRIER_ARRIVE(sb + SMEM_EMPTY + 8 * s);
                    if (!(last_tile && k == NK - 1)) {
                        const int sN  = (s + 1 == DEPTH) ? 0 : s + 1;
                        const int phN = (s + 1 == DEPTH) ? (ph ^ 1) : ph;
                        MBARRIER_WAIT_PARITY(sb + SMEM_FULL + 8 * sN, phN);
                        uint32_t sAN = sb + SMEM_A0 + sN * STAGE_A;
                        uint32_t sBN = sb + SMEM_B0 + sN * STAGE_B;
#pragma unroll
                        for (int mi = 0; mi < 4; mi++)
                            ldsm_x4(aF[nx][mi], sAN + sw128(aRow + (uint32_t)mi * 2048));
#pragma unroll
                        for (int pi = 0; pi < 2; pi++)
                            ldsm_x4(bF[nx][pi], sBN + sw128(bRow + (uint32_t)pi * 2048));
                        s = sN; ph = phN;
                    }
                }
#pragma unroll
                for (int mi = 0; mi < 4; mi++) {
#pragma unroll
                    for (int pi = 0; pi < 2; pi++) {
                        mma16816(acc[mi][2 * pi],     aF[cur][mi], bF[cur][pi][0], bF[cur][pi][1]);
                        mma16816(acc[mi][2 * pi + 1], aF[cur][mi], bF[cur][pi][2], bF[cur][pi][3]);
                    }
                }
            }
        }

        // -------- Epilogue (producer prefetches next tile meanwhile) -------
        {
            const int row0 = mt * BM + Mbase + (lane >> 2);
#pragma unroll
            for (int ni = 0; ni < 4; ni++) {
                const int col = col0 + ni * 8;
#pragma unroll
                for (int mi = 0; mi < 4; mi++) {
                    const int r = row0 + mi * 16;
                    float2 v0 = make_float2(acc[mi][ni][0] + bv[ni].x, acc[mi][ni][1] + bv[ni].y);
                    float2 v1 = make_float2(acc[mi][ni][2] + bv[ni].x, acc[mi][ni][3] + bv[ni].y);
                    *reinterpret_cast<float2*>(out + (size_t)r * NDIM + col) = v0;
                    *reinterpret_cast<float2*>(out + (size_t)(r + 8) * NDIM + col) = v1;
                }
            }
        }
    }
}

// ============================================================
// Host launcher
// ============================================================
typedef CUresult (*tmap_encode_fn)(
    CUtensorMap*, CUtensorMapDataType, cuuint32_t, void*,
    const cuuint64_t*, const cuuint64_t*, const cuuint32_t*, const cuuint32_t*,
    CUtensorMapInterleave, CUtensorMapSwizzle, CUtensorMapL2promotion,
    CUtensorMapFloatOOBfill);

extern "C" void kernel_launch(void* const* d_in, const int* in_sizes, int n_in,
                              void* d_out, int out_size)
{
    const float* inp  = (const float*)d_in[0];
    const float* wgt  = (const float*)d_in[1];
    const float* bias = (const float*)d_in[2];
    float* out = (float*)d_out;

    const int M = in_sizes[0] / KDIM;  // 16384
    const int N = in_sizes[1] / KDIM;  // 4096

    void *qx_ptr = nullptr, *qw_ptr = nullptr;
    cudaGetSymbolAddress(&qx_ptr, g_qx);
    cudaGetSymbolAddress(&qw_ptr, g_qw);

    // Persistent grid = #SMs (152 on GB300; attribute query is capture-safe)
    int nsm = 148;
    {
        int v = 0, dev = 0;
        cudaGetDevice(&dev);
        if (cudaDeviceGetAttribute(&v, cudaDevAttrMultiProcessorCount, dev)
                == cudaSuccess && v > 0)
            nsm = v;
    }

    // -------- quantize both operands (one fused launch; round-11 proven) ---
    {
        int gx = M * (KDIM / GROUP);
        int gw = N * (KDIM / GROUP);
        int total = gx + gw;
        bfp_quant_fused_kernel<<<(total + 255) / 256, 256>>>(
            inp, (__nv_bfloat16*)qx_ptr, gx,
            wgt, (__nv_bfloat16*)qw_ptr, gw);
    }

    // -------- tensor maps (host-side, capture-safe) --------
    tmap_encode_fn encode = nullptr;
    {
        cudaDriverEntryPointQueryResult qres;
        void* fn = nullptr;
        if (cudaGetDriverEntryPointByVersion("cuTensorMapEncodeTiled", &fn, 12000,
                                             cudaEnableDefault, &qres) != cudaSuccess ||
            fn == nullptr) {
            cudaGetDriverEntryPoint("cuTensorMapEncodeTiled", &fn,
                                    cudaEnableDefault, &qres);
        }
        encode = (tmap_encode_fn)fn;
    }

    CUtensorMap mapA, mapB;
    {
        cuuint64_t dims[2]    = {(cuuint64_t)KDIM, (cuuint64_t)M};
        cuuint64_t strides[1] = {(cuuint64_t)KDIM * sizeof(__nv_bfloat16)};
        cuuint32_t box[2]     = {64, BM};   // 64 bf16 = 128 B rows (SW128 limit)
        cuuint32_t es[2]      = {1, 1};
        encode(&mapA, CU_TENSOR_MAP_DATA_TYPE_BFLOAT16, 2, qx_ptr,
               dims, strides, box, es,
               CU_TENSOR_MAP_INTERLEAVE_NONE, CU_TENSOR_MAP_SWIZZLE_128B,
               CU_TENSOR_MAP_L2_PROMOTION_L2_128B, CU_TENSOR_MAP_FLOAT_OOB_FILL_NONE);
    }
    {
        cuuint64_t dims[2]    = {(cuuint64_t)KDIM, (cuuint64_t)N};
        cuuint64_t strides[1] = {(cuuint64_t)KDIM * sizeof(__nv_bfloat16)};
        cuuint32_t box[2]     = {64, BN};
        cuuint32_t es[2]      = {1, 1};
        encode(&mapB, CU_TENSOR_MAP_DATA_TYPE_BFLOAT16, 2, qw_ptr,
               dims, strides, box, es,
               CU_TENSOR_MAP_INTERLEAVE_NONE, CU_TENSOR_MAP_SWIZZLE_128B,
               CU_TENSOR_MAP_L2_PROMOTION_L2_128B, CU_TENSOR_MAP_FLOAT_OOB_FILL_NONE);
    }

    // -------- GEMM (persistent, 1 CTA/SM on ALL SMs, PDL overlap) --------
    cudaFuncSetAttribute(bfp_gemm_kernel,
                         cudaFuncAttributeMaxDynamicSharedMemorySize, SMEM_TOTAL);

    cudaLaunchConfig_t cfg = {};
    cfg.gridDim  = dim3(nsm, 1, 1);
    cfg.blockDim = dim3(NTHREADS, 1, 1);
    cfg.dynamicSmemBytes = SMEM_TOTAL;
    cfg.stream = 0;   // same (default) stream the harness captures
    cudaLaunchAttribute attrs[1];
    attrs[0].id = cudaLaunchAttributeProgrammaticStreamSerialization;
    attrs[0].val.programmaticStreamSerializationAllowed = 1;
    cfg.attrs = attrs;
    cfg.numAttrs = 1;

    cudaError_t lerr = cudaLaunchKernelEx(&cfg, bfp_gemm_kernel,
                                          mapA, mapB, bias, out);
    if (lerr != cudaSuccess) {
        // Fallback: plain serialized launch (identical to round-11 behavior).
        bfp_gemm_kernel<<<nsm, NTHREADS, SMEM_TOTAL>>>(mapA, mapB, bias, out);
    }
}

// round 17
// speedup vs baseline: 1.0469x; 1.0046x over previous
#include <cuda_runtime.h>
#include <cuda.h>
#include <cuda_bf16.h>
#include <cstdint>

// ============================================================
// Problem constants
// ============================================================
#define KDIM 4096
#define NDIM 4096
#define GROUP 16

#define BM 128
#define BN 128
#define BK 128                   // per stage (two 64-col SW128 sub-tiles)
#define DEPTH 3
#define NK (KDIM / BK)           // 32 k-iterations per tile
#define NTHREADS 320             // 8 compute + 1 producer + 1 quant warp
#define NTILES 4096              // (16384/128) * (4096/128)

#define NGX (16384 * 256)        // X groups (4,194,304) = 128 blocks x 32768
#define NGW (4096 * 256)         // W groups (1,048,576)
#define XPRE_BLOCKS 8            // X rows [0,1024) quantized in phase 1
#define GROUPS_PER_BLOCK 32768   // 128 rows x 256 groups/row

// ============================================================
// Scratch (device globals: allocation-free rule)
// ============================================================
__device__ __align__(256) __nv_bfloat16 g_qx[(size_t)16384 * KDIM]; // 128 MB
__device__ __align__(256) __nv_bfloat16 g_qw[(size_t)NDIM * KDIM];  //  32 MB
__device__ unsigned g_bar;            // ticket grid barrier (monotonic)
__device__ unsigned g_blkdone[128];   // per-128-row X block quant counters

// ============================================================
// PTX helpers (baseline PTX — toolchain targets sm_103, no tcgen05)
// ============================================================
__device__ __forceinline__ uint32_t smem_to_u32(const void* smem_ptr) {
    uint32_t addr;
    asm("{ .reg .u64 tmp; cvta.to.shared.u64 tmp, %1; cvt.u32.u64 %0, tmp; }"
        : "=r"(addr) : "l"(smem_ptr));
    return addr;
}

#define MBARRIER_INIT(mbar, count) \
    asm volatile("mbarrier.init.shared.b64 [%0], %1;" \
        :: "r"((uint32_t)(mbar)), "r"((uint32_t)(count)) : "memory")

#define MBARRIER_EXPECT_TX(mbar, tx_bytes) \
    asm volatile("mbarrier.arrive.expect_tx.shared.b64 _, [%0], %1;" \
        :: "r"((uint32_t)(mbar)), "r"((uint32_t)(tx_bytes)) : "memory")

#define MBARRIER_ARRIVE(mbar) \
    asm volatile("mbarrier.arrive.shared.b64 _, [%0];" \
        :: "r"((uint32_t)(mbar)) : "memory")

#define MBARRIER_WAIT_PARITY(mbar, parity) do { \
    uint32_t _m = (uint32_t)(mbar); \
    uint32_t _p = (uint32_t)(parity); \
    uint32_t _done; \
    asm volatile( \
        "{\n\t.reg .pred p;\n\t" \
        "mbarrier.try_wait.parity.acquire.cta.shared::cta.b64 p, [%1], %2;\n\t" \
        "selp.b32 %0, 1, 0, p;\n\t}" \
        : "=r"(_done) : "r"(_m), "r"(_p) : "memory"); \
    if (!_done) { \
        asm volatile( \
            "{\n\t.reg .pred P1;\n\t" \
            "WAIT_LOOP_%=:\n\t" \
            "mbarrier.try_wait.parity.acquire.cta.shared::cta.b64 P1, [%0], %1, 0x989680;\n\t" \
            "@P1 bra.uni WAIT_DONE_%=;\n\t" \
            "bra.uni WAIT_LOOP_%=;\n\t" \
            "WAIT_DONE_%=:\n\t}" \
            :: "r"(_m), "r"(_p) : "memory"); \
    } \
} while (0)

__device__ __forceinline__ void tma_load_2d(
    uint32_t smem_addr, const void* tensor_map,
    int32_t cx, int32_t cy, uint32_t mbar)
{
    asm volatile(
        "cp.async.bulk.tensor.2d.shared::cta.global.tile.mbarrier::complete_tx::bytes "
        "[%0], [%1, {%2, %3}], [%4];"
        :: "r"(smem_addr), "l"(tensor_map), "r"(cx), "r"(cy), "r"(mbar)
        : "memory");
}

// SW128 swizzle (matches TMA CU_TENSOR_MAP_SWIZZLE_128B)
__device__ __forceinline__ uint32_t sw128(uint32_t o) {
    return o ^ ((o >> 3) & 0x70);
}

__device__ __forceinline__ void ldsm_x4(uint32_t* r, uint32_t addr) {
    asm volatile(
        "ldmatrix.sync.aligned.m8n8.x4.shared.b16 {%0,%1,%2,%3}, [%4];"
        : "=r"(r[0]), "=r"(r[1]), "=r"(r[2]), "=r"(r[3]) : "r"(addr));
}

__device__ __forceinline__ void mma16816(float* c, const uint32_t* a,
                                         uint32_t b0, uint32_t b1) {
    asm volatile(
        "mma.sync.aligned.m16n8k16.row.col.f32.bf16.bf16.f32 "
        "{%0,%1,%2,%3}, {%4,%5,%6,%7}, {%8,%9}, {%0,%1,%2,%3};"
        : "+f"(c[0]), "+f"(c[1]), "+f"(c[2]), "+f"(c[3])
        : "r"(a[0]), "r"(a[1]), "r"(a[2]), "r"(a[3]), "r"(b0), "r"(b1));
}

// ============================================================
// BFP quantize one group of 16 from registers (exact bf16 values)
// ============================================================
__device__ __forceinline__ void quant_group_regs(const float4& f0, const float4& f1,
                                                 const float4& f2, const float4& f3,
                                                 uint4* dst)
{
    float v[GROUP] = {f0.x, f0.y, f0.z, f0.w, f1.x, f1.y, f1.z, f1.w,
                      f2.x, f2.y, f2.z, f2.w, f3.x, f3.y, f3.z, f3.w};
    float m = 0.f;
#pragma unroll
    for (int i = 0; i < GROUP; i++) m = fmaxf(m, fabsf(v[i]));

    union { __nv_bfloat16 h[GROUP]; uint4 u[2]; } pk;
    if (m > 0.f) {
        unsigned e = __float_as_uint(m) >> 23;   // biased exp = 127+floor(log2 m)
        if (e < 8u) e = 8u;
        float scale = __uint_as_float((e - 7u) << 23);     // 2^(exp-7)
        float inv   = __uint_as_float((261u - e) << 23);   // 2^(7-exp) exact
#pragma unroll
        for (int i = 0; i < GROUP; i++) {
            float r = rintf(v[i] * inv);                   // round-half-even
            r = fminf(127.f, fmaxf(-127.f, r));
            pk.h[i] = __float2bfloat16(r * scale);         // exact in bf16
        }
    } else {
#pragma unroll
        for (int i = 0; i < GROUP; i++) pk.h[i] = __float2bfloat16(0.f);
    }
    dst[0] = pk.u[0];
    dst[1] = pk.u[1];
}

// Quantize a PAIR of adjacent groups: 8 LDG.128 up-front (MLP=8), evict-first.
__device__ __forceinline__ void quant_pair(const float* __restrict__ src_base,
                                           __nv_bfloat16* __restrict__ dst_base,
                                           int g0)
{
    const float4* src = reinterpret_cast<const float4*>(src_base + (size_t)g0 * GROUP);
    float4 r[8];
#pragma unroll
    for (int i = 0; i < 8; i++) r[i] = __ldcs(src + i);
    uint4 outp[4];
    quant_group_regs(r[0], r[1], r[2], r[3], outp);
    quant_group_regs(r[4], r[5], r[6], r[7], outp + 2);
    uint4* dst = reinterpret_cast<uint4*>(dst_base + (size_t)g0 * GROUP);
#pragma unroll
    for (int i = 0; i < 4; i++) dst[i] = outp[i];
}

// ============================================================
// Fused persistent kernel:
//  Phase 1 (all 320 threads): quantize W + X rows [0,1024);
//                             CTA 0 resets block counters.
//  Ticket grid barrier (152 co-resident CTAs; replay-safe monotone ticket).
//  Phase 2: warps 0-7 compute + warp 8 TMA producer = round-11/16 proven
//           GEMM (producer additionally spin-waits g_blkdone[mt] for
//           mt >= 8); warp 9 quantizes X blocks 8..127 in order and
//           publishes progress (threadfence + atomicAdd).
// ============================================================
static constexpr int SMEM_FULL  = 0;
static constexpr int SMEM_EMPTY = SMEM_FULL + 8 * DEPTH;
static constexpr int SUB      = 16384;                      // 128x64 bf16 sub-tile
static constexpr int STAGE_A  = 2 * SUB;                    // 32768 B
static constexpr int STAGE_B  = 2 * SUB;                    // 32768 B
static constexpr int SMEM_A0  = 1024;
static constexpr int SMEM_B0  = SMEM_A0 + DEPTH * STAGE_A;  // 99328
static constexpr int SMEM_TOTAL = SMEM_B0 + DEPTH * STAGE_B; // 197632
static constexpr unsigned STAGE_BYTES = (unsigned)(STAGE_A + STAGE_B); // 65536

__global__ void __launch_bounds__(NTHREADS, 1) bfp_fused_kernel(
    const __grid_constant__ CUtensorMap tma_a,
    const __grid_constant__ CUtensorMap tma_b,
    const float* __restrict__ inp,
    const float* __restrict__ wgt,
    const float* __restrict__ bias,
    float* __restrict__ out)
{
    extern __shared__ char smem[];
    uint32_t sb = smem_to_u32(smem);
    const int tid  = threadIdx.x;
    const int wid  = tid >> 5;
    const int lane = tid & 31;
    const int bid  = blockIdx.x;
    const int stride = gridDim.x;

    if (tid == 0) {
#pragma unroll
        for (int s = 0; s < DEPTH; s++) {
            MBARRIER_INIT(sb + SMEM_FULL  + 8 * s, 1);
            MBARRIER_INIT(sb + SMEM_EMPTY + 8 * s, 8);  // 8 compute warps
        }
    }
    // Reset X-block progress counters (before barrier; increments are after).
    if (bid == 0 && tid < 128) g_blkdone[tid] = 0u;

    // ---------------- Phase 1: quantize W + X prefix (all threads) --------
    {
        const int total1 = NGW + XPRE_BLOCKS * GROUPS_PER_BLOCK; // 1,310,720
        const int npairs = total1 >> 1;
        const int gtid = bid * NTHREADS + tid;
        const int gstr = stride * NTHREADS;
#pragma unroll 1
        for (int p = gtid; p < npairs; p += gstr) {
            int g0 = 2 * p;
            if (g0 < NGW) quant_pair(wgt, g_qw, g0);          // pair fully in W
            else          quant_pair(inp, g_qx, g0 - NGW);    // pair fully in X prefix
        }
    }

    // ---------------- Grid barrier (ticket; replay-safe monotone) ---------
    __threadfence();
    __syncthreads();
    if (tid == 0) {
        unsigned ticket = atomicAdd(&g_bar, 1u);
        unsigned target = ticket - (ticket % (unsigned)stride) + (unsigned)stride;
        unsigned cur;
        do {
            __nanosleep(128);
            cur = *(volatile unsigned*)&g_bar;
        } while ((int)(cur - target) < 0);
        __threadfence();
    }
    __syncthreads();

    // ---------------- Phase 2 ----------------
    if (wid == 9) {
        // Background X-quant: blocks 8..127 in order, publish progress.
        const int qid  = bid * 32 + lane;
        const int qstr = stride * 32;
#pragma unroll 1
        for (int blk = XPRE_BLOCKS; blk < 128; blk++) {
            const int base = blk * GROUPS_PER_BLOCK;
            unsigned cnt = 0;
#pragma unroll 1
            for (int i = qid; i < GROUPS_PER_BLOCK; i += qstr) {
                const int g = base + i;
                const float4* src = reinterpret_cast<const float4*>(
                    inp + (size_t)g * GROUP);
                float4 r0 = __ldcs(src), r1 = __ldcs(src + 1),
                       r2 = __ldcs(src + 2), r3 = __ldcs(src + 3);
                uint4 o[2];
                quant_group_regs(r0, r1, r2, r3, o);
                uint4* dst = reinterpret_cast<uint4*>(g_qx + (size_t)g * GROUP);
                dst[0] = o[0];
                dst[1] = o[1];
                cnt++;
            }
            __threadfence();
            atomicAdd(&g_blkdone[blk], cnt);
        }
        return;
    }

    if (wid == 8) {
        // ---------------- TMA producer (persistent, ring continuous) -------
        if (lane == 0) {
            asm volatile("fence.proxy.async;" ::: "memory");
            int s = 0, wph = 0;
            int git = 0;
#pragma unroll 1
            for (int t = bid; t < NTILES; t += stride) {
                const int nt = t & 31;
                const int mt = t >> 5;
                if (mt >= XPRE_BLOCKS) {
                    // Wait until X block mt is fully quantized.
                    unsigned v;
                    do {
                        asm volatile("ld.acquire.gpu.global.u32 %0, [%1];"
                                     : "=r"(v) : "l"(&g_blkdone[mt]) : "memory");
                        if (v >= (unsigned)GROUPS_PER_BLOCK) break;
                        __nanosleep(64);
                    } while (true);
                }
#pragma unroll 1
                for (int k = 0; k < NK; k++, git++) {
                    if (git >= DEPTH) MBARRIER_WAIT_PARITY(sb + SMEM_EMPTY + 8 * s, wph);
                    uint32_t fb = sb + SMEM_FULL + 8 * s;
                    MBARRIER_EXPECT_TX(fb, STAGE_BYTES);
                    uint32_t aDst = sb + SMEM_A0 + s * STAGE_A;
                    uint32_t bDst = sb + SMEM_B0 + s * STAGE_B;
                    tma_load_2d(aDst,       (const void*)&tma_a, k * BK,      mt * BM, fb);
                    tma_load_2d(aDst + SUB, (const void*)&tma_a, k * BK + 64, mt * BM, fb);
                    tma_load_2d(bDst,       (const void*)&tma_b, k * BK,      nt * BN, fb);
                    tma_load_2d(bDst + SUB, (const void*)&tma_b, k * BK + 64, nt * BN, fb);
                    if (++s == DEPTH) { s = 0; if (git >= DEPTH) wph ^= 1; }
                }
            }
        }
        return;
    }

    // ---------------- Compute warps: 2x4 grid, 64x32 tiles ----------------
    const int wm = wid & 1;            // 2 warps along M
    const int wn = wid >> 1;           // 4 warps along N
    const int Mbase = wm * 64;
    const int Nbase = wn * 32;

    // ldmatrix lane addresses (byte offsets within one 64-col sub-tile;
    // rows are 128 B wide)
    uint32_t aRow = (uint32_t)(Mbase + (lane & 15)) * 128 + ((lane >> 4) & 1) * 16;
    uint32_t bRow = (uint32_t)(Nbase + ((lane >> 4) << 3) + (lane & 7)) * 128
                  + ((lane >> 3) & 1) * 16;

    uint32_t aF[2][4][4];
    uint32_t bF[2][2][4];

    // Prologue: wait stage 0 of the first tile, preload kst0 into buffer 0.
    int s = 0, ph = 0;
    MBARRIER_WAIT_PARITY(sb + SMEM_FULL, 0);
    {
        uint32_t sA = sb + SMEM_A0;
        uint32_t sB = sb + SMEM_B0;
#pragma unroll
        for (int mi = 0; mi < 4; mi++)
            ldsm_x4(aF[0][mi], sA + sw128(aRow + (uint32_t)mi * 2048));
#pragma unroll
        for (int pi = 0; pi < 2; pi++)
            ldsm_x4(bF[0][pi], sB + sw128(bRow + (uint32_t)pi * 2048));
    }

#pragma unroll 1
    for (int t = bid; t < NTILES; t += stride) {
        const int nt = t & 31;
        const int mt = t >> 5;
        const bool last_tile = (t + stride >= NTILES);

        const int col0 = nt * BN + Nbase + 2 * (lane & 3);
        float2 bv[4];
#pragma unroll
        for (int ni = 0; ni < 4; ni++)
            bv[ni] = __ldg((const float2*)(bias + col0 + ni * 8));

        float acc[4][4][4];
#pragma unroll
        for (int mi = 0; mi < 4; mi++)
#pragma unroll
            for (int ni = 0; ni < 4; ni++)
#pragma unroll
                for (int j = 0; j < 4; j++) acc[mi][ni][j] = 0.f;

#pragma unroll 1
        for (int k = 0; k < NK; k++) {
            uint32_t sA = sb + SMEM_A0 + s * STAGE_A;
            uint32_t sB = sb + SMEM_B0 + s * STAGE_B;
#pragma unroll
            for (int kst = 0; kst < 8; kst++) {
                const int cur = kst & 1;
                const int nx  = cur ^ 1;
                if (kst < 7) {
                    // preload next kst of the SAME stage
                    const uint32_t hofs = (uint32_t)(((kst + 1) >> 2) * SUB);
                    const uint32_t kin  = (uint32_t)(((kst + 1) & 3) * 32);
#pragma unroll
                    for (int mi = 0; mi < 4; mi++)
                        ldsm_x4(aF[nx][mi], sA + hofs + sw128(aRow + (uint32_t)mi * 2048 + kin));
#pragma unroll
                    for (int pi = 0; pi < 2; pi++)
                        ldsm_x4(bF[nx][pi], sB + hofs + sw128(bRow + (uint32_t)pi * 2048 + kin));
                } else {
                    // all LDSMs of stage s issued: release buffer, then wait
                    // for the NEXT stage (possibly of the next tile) and
                    // preload its kst0 before the tail MMAs of this stage.
                    if (lane == 0) MBARRIER_ARRIVE(sb + SMEM_EMPTY + 8 * s);
                    if (!(last_tile && k == NK - 1)) {
                        const int sN  = (s + 1 == DEPTH) ? 0 : s + 1;
                        const int phN = (s + 1 == DEPTH) ? (ph ^ 1) : ph;
                        MBARRIER_WAIT_PARITY(sb + SMEM_FULL + 8 * sN, phN);
                        uint32_t sAN = sb + SMEM_A0 + sN * STAGE_A;
                        uint32_t sBN = sb + SMEM_B0 + sN * STAGE_B;
#pragma unroll
                        for (int mi = 0; mi < 4; mi++)
                            ldsm_x4(aF[nx][mi], sAN + sw128(aRow + (uint32_t)mi * 2048));
#pragma unroll
                        for (int pi = 0; pi < 2; pi++)
                            ldsm_x4(bF[nx][pi], sBN + sw128(bRow + (uint32_t)pi * 2048));
                        s = sN; ph = phN;
                    }
                }
#pragma unroll
                for (int mi = 0; mi < 4; mi++) {
#pragma unroll
                    for (int pi = 0; pi < 2; pi++) {
                        mma16816(acc[mi][2 * pi],     aF[cur][mi], bF[cur][pi][0], bF[cur][pi][1]);
                        mma16816(acc[mi][2 * pi + 1], aF[cur][mi], bF[cur][pi][2], bF[cur][pi][3]);
                    }
                }
            }
        }

        // -------- Epilogue (producer prefetches next tile meanwhile) -------
        {
            const int row0 = mt * BM + Mbase + (lane >> 2);
#pragma unroll
            for (int ni = 0; ni < 4; ni++) {
                const int col = col0 + ni * 8;
#pragma unroll
                for (int mi = 0; mi < 4; mi++) {
                    const int r = row0 + mi * 16;
                    float2 v0 = make_float2(acc[mi][ni][0] + bv[ni].x, acc[mi][ni][1] + bv[ni].y);
                    float2 v1 = make_float2(acc[mi][ni][2] + bv[ni].x, acc[mi][ni][3] + bv[ni].y);
                    *reinterpret_cast<float2*>(out + (size_t)r * NDIM + col) = v0;
                    *reinterpret_cast<float2*>(out + (size_t)(r + 8) * NDIM + col) = v1;
                }
            }
        }
    }
}

// ============================================================
// Host launcher
// ============================================================
typedef CUresult (*tmap_encode_fn)(
    CUtensorMap*, CUtensorMapDataType, cuuint32_t, void*,
    const cuuint64_t*, const cuuint64_t*, const cuuint32_t*, const cuuint32_t*,
    CUtensorMapInterleave, CUtensorMapSwizzle, CUtensorMapL2promotion,
    CUtensorMapFloatOOBfill);

extern "C" void kernel_launch(void* const* d_in, const int* in_sizes, int n_in,
                              void* d_out, int out_size)
{
    const float* inp  = (const float*)d_in[0];
    const float* wgt  = (const float*)d_in[1];
    const float* bias = (const float*)d_in[2];
    float* out = (float*)d_out;

    const int M = in_sizes[0] / KDIM;  // 16384
    const int N = in_sizes[1] / KDIM;  // 4096

    void *qx_ptr = nullptr, *qw_ptr = nullptr;
    cudaGetSymbolAddress(&qx_ptr, g_qx);
    cudaGetSymbolAddress(&qw_ptr, g_qw);

    // Persistent grid = #SMs (152 on GB300; attribute query is capture-safe)
    int nsm = 148;
    {
        int v = 0, dev = 0;
        cudaGetDevice(&dev);
        if (cudaDeviceGetAttribute(&v, cudaDevAttrMultiProcessorCount, dev)
                == cudaSuccess && v > 0)
            nsm = v;
    }

    // -------- tensor maps (host-side, capture-safe) --------
    tmap_encode_fn encode = nullptr;
    {
        cudaDriverEntryPointQueryResult qres;
        void* fn = nullptr;
        if (cudaGetDriverEntryPointByVersion("cuTensorMapEncodeTiled", &fn, 12000,
                                             cudaEnableDefault, &qres) != cudaSuccess ||
            fn == nullptr) {
            cudaGetDriverEntryPoint("cuTensorMapEncodeTiled", &fn,
                                    cudaEnableDefault, &qres);
        }
        encode = (tmap_encode_fn)fn;
    }

    CUtensorMap mapA, mapB;
    {
        cuuint64_t dims[2]    = {(cuuint64_t)KDIM, (cuuint64_t)M};
        cuuint64_t strides[1] = {(cuuint64_t)KDIM * sizeof(__nv_bfloat16)};
        cuuint32_t box[2]     = {64, BM};   // 64 bf16 = 128 B rows (SW128 limit)
        cuuint32_t es[2]      = {1, 1};
        encode(&mapA, CU_TENSOR_MAP_DATA_TYPE_BFLOAT16, 2, qx_ptr,
               dims, strides, box, es,
               CU_TENSOR_MAP_INTERLEAVE_NONE, CU_TENSOR_MAP_SWIZZLE_128B,
               CU_TENSOR_MAP_L2_PROMOTION_L2_128B, CU_TENSOR_MAP_FLOAT_OOB_FILL_NONE);
    }
    {
        cuuint64_t dims[2]    = {(cuuint64_t)KDIM, (cuuint64_t)N};
        cuuint64_t strides[1] = {(cuuint64_t)KDIM * sizeof(__nv_bfloat16)};
        cuuint32_t box[2]     = {64, BN};
        cuuint32_t es[2]      = {1, 1};
        encode(&mapB, CU_TENSOR_MAP_DATA_TYPE_BFLOAT16, 2, qw_ptr,
               dims, strides, box, es,
               CU_TENSOR_MAP_INTERLEAVE_NONE, CU_TENSOR_MAP_SWIZZLE_128B,
               CU_TENSOR_MAP_L2_PROMOTION_L2_128B, CU_TENSOR_MAP_FLOAT_OOB_FILL_NONE);
    }

    // -------- Fused quant+GEMM (persistent, 1 CTA/SM on ALL SMs) --------
    cudaFuncSetAttribute(bfp_fused_kernel,
                         cudaFuncAttributeMaxDynamicSharedMemorySize, SMEM_TOTAL);
    bfp_fused_kernel<<<nsm, NTHREADS, SMEM_TOTAL>>>(mapA, mapB, inp, wgt,
                                                    bias, out);
}